// round 1
// baseline (speedup 1.0000x reference)
#include <cuda_runtime.h>
#include <math.h>

#define Bc 32
#define Oc 32
#define Ic 2048
#define Vc 32
#define Dc 16

// ---- scratch (static device allocations; no cudaMalloc anywhere) ----
__device__ float g_uhat[(size_t)Bc * Oc * Ic * Vc];  // 256 MB
__device__ float g_logits[Bc * Oc * Ic];             // 8 MB
__device__ float g_s[Bc * Oc * Vc];                  // 128 KB
__device__ float g_out0[Bc * Oc * Vc];
__device__ float g_out1[Bc * Oc * Vc];

// ---------------------------------------------------------------------
// zero the s accumulator
__global__ void zero_s_kernel() {
    int i = blockIdx.x * blockDim.x + threadIdx.x;
    if (i < Bc * Oc * Vc) g_s[i] = 0.0f;
}

// ---------------------------------------------------------------------
// K1: u_hat[b,o,i,v] = sum_d W[o,i,v,d] * x[b,i,d], fused with
//     s0[b,o,v] += (1/32) * sum_i u_hat  (c0 is uniform)
// Block: (itile of 8, o). Threads 256 = 8 warps; warp handles 4 b's, lane = v.
__global__ __launch_bounds__(256) void k1_gemm(const float* __restrict__ x,
                                               const float* __restrict__ W) {
    __shared__ float4 Ws4[8 * 4 * 32];  // [i][d4][v]
    __shared__ float4 Xs4[32 * 8 * 4];  // [b][i][d4]

    const int o = blockIdx.y;
    const int i0 = blockIdx.x * 8;
    const int t = threadIdx.x;

    // Load W tile: 8*32*16 floats = 1024 float4, contiguous in global.
    const float4* Wg = reinterpret_cast<const float4*>(W) +
                       ((size_t)o * Ic + i0) * (Vc * Dc / 4);
#pragma unroll
    for (int k = 0; k < 4; k++) {
        int j = t + k * 256;            // 0..1023
        int i = j >> 7;                 // /128
        int rem = j & 127;
        int v = rem >> 2;
        int d4 = rem & 3;
        Ws4[(i * 4 + d4) * 32 + v] = Wg[j];
    }
    // Load x tile: all 32 b, 8 i, 16 d = 1024 float4.
    const float4* Xg = reinterpret_cast<const float4*>(x);
#pragma unroll
    for (int k = 0; k < 4; k++) {
        int j = t + k * 256;
        int b = j >> 5;
        int r = j & 31;                 // i*4 + d4
        Xs4[b * 32 + r] = Xg[(size_t)b * (Ic * Dc / 4) + i0 * 4 + r];
    }
    __syncthreads();

    const int w = t >> 5;
    const int lane = t & 31;
    const int bbase = w * 4;

    float sacc0 = 0.f, sacc1 = 0.f, sacc2 = 0.f, sacc3 = 0.f;

#pragma unroll 1
    for (int i = 0; i < 8; i++) {
        float4 w0 = Ws4[(i * 4 + 0) * 32 + lane];
        float4 w1 = Ws4[(i * 4 + 1) * 32 + lane];
        float4 w2 = Ws4[(i * 4 + 2) * 32 + lane];
        float4 w3 = Ws4[(i * 4 + 3) * 32 + lane];
#pragma unroll
        for (int bl = 0; bl < 4; bl++) {
            int b = bbase + bl;
            float4 x0 = Xs4[(b * 8 + i) * 4 + 0];
            float4 x1 = Xs4[(b * 8 + i) * 4 + 1];
            float4 x2 = Xs4[(b * 8 + i) * 4 + 2];
            float4 x3 = Xs4[(b * 8 + i) * 4 + 3];
            float u = w0.x * x0.x + w0.y * x0.y + w0.z * x0.z + w0.w * x0.w +
                      w1.x * x1.x + w1.y * x1.y + w1.z * x1.z + w1.w * x1.w +
                      w2.x * x2.x + w2.y * x2.y + w2.z * x2.z + w2.w * x2.w +
                      w3.x * x3.x + w3.y * x3.y + w3.z * x3.z + w3.w * x3.w;
            g_uhat[(((size_t)b * Oc + o) * Ic + (i0 + i)) * Vc + lane] = u;
            if (bl == 0) sacc0 += u;
            else if (bl == 1) sacc1 += u;
            else if (bl == 2) sacc2 += u;
            else sacc3 += u;
        }
    }
    const float scale = 1.0f / (float)Oc;
    atomicAdd(&g_s[((bbase + 0) * Oc + o) * Vc + lane], sacc0 * scale);
    atomicAdd(&g_s[((bbase + 1) * Oc + o) * Vc + lane], sacc1 * scale);
    atomicAdd(&g_s[((bbase + 2) * Oc + o) * Vc + lane], sacc2 * scale);
    atomicAdd(&g_s[((bbase + 3) * Oc + o) * Vc + lane], sacc3 * scale);
}

// ---------------------------------------------------------------------
// squash: reads g_s, writes g_out0 (which=0), g_out1 (which=1), or ext (which=2)
// One warp per (b,o) row of 32 v's. Optionally re-zeros g_s for the next pass.
__global__ __launch_bounds__(256) void squash_kernel(int which, float* __restrict__ ext,
                                                     int zero_after) {
    int g = blockIdx.x * 8 + (threadIdx.x >> 5);  // (b*32+o), 0..1023
    int lane = threadIdx.x & 31;
    float s = g_s[g * 32 + lane];
    float sq = s * s;
#pragma unroll
    for (int st = 16; st >= 1; st >>= 1) sq += __shfl_xor_sync(0xffffffffu, sq, st);
    float val = (sq / (1.0f + sq)) * rsqrtf(sq + 1e-8f) * s;
    float* dst = (which == 0) ? g_out0 : (which == 1) ? g_out1 : ext;
    dst[g * 32 + lane] = val;
    if (zero_after) g_s[g * 32 + lane] = 0.0f;
}

// ---------------------------------------------------------------------
// Routing pass (iter = 1 or 2), fused: a = out_prev . u_hat ; logits update ;
// softmax over o ; s += c * u_hat.   One u_hat read serves both a and s.
// Block: (ichunk of 256, b). 8 warps; warp handles 32 consecutive i; lane = v.
__global__ __launch_bounds__(256, 2) void route_kernel(int iter) {
    __shared__ float out_s[Oc * Vc];   // [o][v]
    __shared__ float bl_s[Oc * 257];   // logits tile [o][il], padded

    const int b = blockIdx.y;
    const int i0 = blockIdx.x * 256;
    const int t = threadIdx.x;

    const float* out_prev = (iter == 1) ? g_out0 : g_out1;
    for (int k = t; k < Oc * Vc; k += 256) out_s[k] = out_prev[b * (Oc * Vc) + k];
    if (iter == 2) {
        for (int k = t; k < Oc * 256; k += 256) {
            int o = k >> 8, il = k & 255;
            bl_s[o * 257 + il] = g_logits[((size_t)b * Oc + o) * Ic + i0 + il];
        }
    }
    __syncthreads();

    const int w = t >> 5;
    const int lane = t & 31;

    float s_reg[32];
#pragma unroll
    for (int o = 0; o < 32; o++) s_reg[o] = 0.0f;

    const float* ub = g_uhat + (size_t)b * Oc * Ic * Vc;

#pragma unroll 1
    for (int ii = 0; ii < 32; ii++) {
        int il = w * 32 + ii;
        int i = i0 + il;

        // load u_hat[b, o, i, lane] for all o — 32 coalesced 128B loads
        float u[32];
        const float* up = ub + (size_t)i * Vc + lane;
#pragma unroll
        for (int o = 0; o < 32; o++) u[o] = up[(size_t)o * Ic * Vc];

        // p[o] = u[o] * out_prev[o, lane]
        float q[32];
#pragma unroll
        for (int o = 0; o < 32; o++) q[o] = u[o] * out_s[o * 32 + lane];

        // transpose-reduce over v: after this, lane o holds a[o] = sum_v p[v][o]
#pragma unroll
        for (int st = 16; st >= 1; st >>= 1) {
            bool hi = (lane & st) != 0;
#pragma unroll
            for (int k = 0; k < 16; k++) {
                if (k < st) {
                    float send = hi ? q[k] : q[k + st];
                    float recv = __shfl_xor_sync(0xffffffffu, send, st);
                    q[k] = (hi ? q[k + st] : q[k]) + recv;
                }
            }
        }
        float L = q[0];
        if (iter == 2) L += bl_s[lane * 257 + il];
        else           bl_s[lane * 257 + il] = L;   // stage b1 for coalesced write

        // softmax over o (o == lane now)
        float m = L;
#pragma unroll
        for (int st = 16; st >= 1; st >>= 1) m = fmaxf(m, __shfl_xor_sync(0xffffffffu, m, st));
        float e = __expf(L - m);
        float sum = e;
#pragma unroll
        for (int st = 16; st >= 1; st >>= 1) sum += __shfl_xor_sync(0xffffffffu, sum, st);
        float c = e / sum;

        // s[o, v=lane] += c[o] * u[o]; broadcast c[o] from lane o
#pragma unroll
        for (int o = 0; o < 32; o++) {
            float cb = __shfl_sync(0xffffffffu, c, o);
            s_reg[o] += cb * u[o];
        }
    }

#pragma unroll
    for (int o = 0; o < 32; o++)
        atomicAdd(&g_s[(b * Oc + o) * Vc + lane], s_reg[o]);

    if (iter == 1) {
        __syncthreads();
        for (int k = t; k < Oc * 256; k += 256) {
            int o = k >> 8, il = k & 255;
            g_logits[((size_t)b * Oc + o) * Ic + i0 + il] = bl_s[o * 257 + il];
        }
    }
}

// ---------------------------------------------------------------------
extern "C" void kernel_launch(void* const* d_in, const int* in_sizes, int n_in,
                              void* d_out, int out_size) {
    const float* x = (const float*)d_in[0];
    const float* W = (const float*)d_in[1];
    if (n_in >= 2 && in_sizes[0] > in_sizes[1]) {  // robust to input ordering
        x = (const float*)d_in[1];
        W = (const float*)d_in[0];
    }
    float* out = (float*)d_out;

    zero_s_kernel<<<128, 256>>>();
    k1_gemm<<<dim3(Ic / 8, Oc), 256>>>(x, W);          // u_hat + s0
    squash_kernel<<<128, 256>>>(0, nullptr, 1);        // out0 = squash(s0), zero s
    route_kernel<<<dim3(Ic / 256, Bc), 256>>>(1);      // a0 -> b1 -> c1 -> s1
    squash_kernel<<<128, 256>>>(1, nullptr, 1);        // out1 = squash(s1), zero s
    route_kernel<<<dim3(Ic / 256, Bc), 256>>>(2);      // a1 -> b2 -> c2 -> s2
    squash_kernel<<<128, 256>>>(2, out, 0);            // final output
}

// round 3
// speedup vs baseline: 1.0079x; 1.0079x over previous
#include <cuda_runtime.h>
#include <cuda_fp16.h>
#include <math.h>

#define Bc 32
#define Oc 32
#define Ic 2048
#define Vc 32
#define Dc 16

// ---- scratch (static device arrays; no allocation anywhere) ----
// u_hat stored fp16, layout [b][i][o][v] : one (b,i) tile = 1024 halfs = 2KB contiguous
__device__ __half g_uhat[(size_t)Bc * Ic * Oc * Vc];   // 128 MB
__device__ float  g_logits[(size_t)Bc * Ic * Oc];      // [b][i][o], 8 MB
__device__ float  g_sbuf[3][Bc * Oc * Vc];             // s0, s1, s2

// ---------------------------------------------------------------------
__global__ void zero_s_kernel() {
    int i = blockIdx.x * blockDim.x + threadIdx.x;
    if (i < 3 * Bc * Oc * Vc) ((float*)g_sbuf)[i] = 0.0f;
}

// ---------------------------------------------------------------------
// K1: u_hat[b,i,o,v] = sum_d W[o,i,v,d] * x[b,i,d]  (fp32 math, fp16 store)
//     fused with s0[b,o,v] += (1/32) * sum_i u_hat (c0 uniform).
// Packed f32x2 FMA: each instr does the MAC for 2 batches at once.
// Block: (i-tile of 8, o). 256 thr = 8 warps; warp owns 4 b's (2 pairs); lane = v.
__global__ __launch_bounds__(256) void k1_gemm(const float* __restrict__ x,
                                               const float* __restrict__ W) {
    __shared__ float4 Ws4[8 * 4 * 32];                 // [i][d4][v] 16 KB
    __shared__ unsigned long long Xp[16 * 8 * 16];     // [bpair][i][d] packed {b_even,b_odd} 16 KB

    const int o = blockIdx.y;
    const int i0 = blockIdx.x * 8;
    const int t = threadIdx.x;

    // W tile: 8*32*16 floats = 1024 float4, contiguous.
    const float4* Wg = reinterpret_cast<const float4*>(W) +
                       ((size_t)o * Ic + i0) * (Vc * Dc / 4);
#pragma unroll
    for (int k = 0; k < 4; k++) {
        int j = t + k * 256;
        int i = j >> 7;
        int rem = j & 127;
        int v = rem >> 2;
        int d4 = rem & 3;
        Ws4[(i * 4 + d4) * 32 + v] = Wg[j];
    }
    // x tile, packed by batch-pair: Xp[pair][i][d] = {x[2p][i][d], x[2p+1][i][d]}
    const float4* Xg = reinterpret_cast<const float4*>(x);
#pragma unroll
    for (int k = 0; k < 4; k++) {
        int j = t + k * 256;
        int b = j >> 5;
        int r = j & 31;                 // i_local*4 + d4
        int il = r >> 2, d4 = r & 3;
        float4 val = Xg[(size_t)b * (Ic * Dc / 4) + i0 * 4 + r];
        float* dst = ((float*)&Xp[((b >> 1) * 8 + il) * 16 + d4 * 4]) + (b & 1);
        dst[0] = val.x; dst[2] = val.y; dst[4] = val.z; dst[6] = val.w;
    }
    __syncthreads();

    const int w = t >> 5;
    const int lane = t & 31;
    const int bbase = w * 4;

    float s0 = 0.f, s1 = 0.f, s2 = 0.f, s3 = 0.f;

#pragma unroll 1
    for (int i = 0; i < 8; i++) {
        float4 w0 = Ws4[(i * 4 + 0) * 32 + lane];
        float4 w1 = Ws4[(i * 4 + 1) * 32 + lane];
        float4 w2 = Ws4[(i * 4 + 2) * 32 + lane];
        float4 w3 = Ws4[(i * 4 + 3) * 32 + lane];
        float wv[16] = {w0.x, w0.y, w0.z, w0.w, w1.x, w1.y, w1.z, w1.w,
                        w2.x, w2.y, w2.z, w2.w, w3.x, w3.y, w3.z, w3.w};
        unsigned long long a01 = 0ull, a23 = 0ull;
        const unsigned long long* x0 = Xp + ((w * 2 + 0) * 8 + i) * 16;
        const unsigned long long* x1 = Xp + ((w * 2 + 1) * 8 + i) * 16;
#pragma unroll
        for (int d = 0; d < 16; d++) {
            unsigned long long wp;
            asm("mov.b64 %0, {%1, %1};" : "=l"(wp) : "f"(wv[d]));
            asm("fma.rn.f32x2 %0, %1, %2, %0;" : "+l"(a01) : "l"(wp), "l"(x0[d]));
            asm("fma.rn.f32x2 %0, %1, %2, %0;" : "+l"(a23) : "l"(wp), "l"(x1[d]));
        }
        float u0, u1, u2, u3;
        asm("mov.b64 {%0, %1}, %2;" : "=f"(u0), "=f"(u1) : "l"(a01));
        asm("mov.b64 {%0, %1}, %2;" : "=f"(u2), "=f"(u3) : "l"(a23));

        size_t ib = (size_t)(i0 + i) * (Oc * Vc) + o * Vc + lane;
        const size_t bstride = (size_t)Ic * Oc * Vc;
        g_uhat[(size_t)(bbase + 0) * bstride + ib] = __float2half_rn(u0);
        g_uhat[(size_t)(bbase + 1) * bstride + ib] = __float2half_rn(u1);
        g_uhat[(size_t)(bbase + 2) * bstride + ib] = __float2half_rn(u2);
        g_uhat[(size_t)(bbase + 3) * bstride + ib] = __float2half_rn(u3);
        s0 += u0; s1 += u1; s2 += u2; s3 += u3;
    }
    const float scale = 1.0f / (float)Oc;
    atomicAdd(&g_sbuf[0][((bbase + 0) * Oc + o) * Vc + lane], s0 * scale);
    atomicAdd(&g_sbuf[0][((bbase + 1) * Oc + o) * Vc + lane], s1 * scale);
    atomicAdd(&g_sbuf[0][((bbase + 2) * Oc + o) * Vc + lane], s2 * scale);
    atomicAdd(&g_sbuf[0][((bbase + 3) * Oc + o) * Vc + lane], s3 * scale);
}

// ---------------------------------------------------------------------
// Routing pass, fully fused: out_prev = squash(s_prev) computed inline;
// a = out_prev . u_hat ; logits ; softmax over o ; s_next += c * u_hat.
// Block: 128 thr = 4 warps, each warp 32 consecutive i. grid (16, B).
// Thread (j = lane/4, q = lane%4) owns fragments (o = j+8f, v = 8q..8q+7), f=0..3.
__global__ __launch_bounds__(128, 4) void route_kernel(int iter) {
    const int b = blockIdx.y;
    const int t = threadIdx.x;
    const int w = t >> 5;
    const int lane = t & 31;
    const int j = lane >> 2;
    const int q = lane & 3;

    const float* s_prev = g_sbuf[iter - 1];
    float* s_next = g_sbuf[iter];

    // inline squash: out_f[f*8+v'] = squash(s_prev)[o=8f+j][v=8q+v']
    float out_f[32];
#pragma unroll
    for (int f = 0; f < 4; f++) {
        const float4* p = (const float4*)(s_prev + ((b * Oc + 8 * f + j) * Vc + 8 * q));
        float4 A = p[0], B = p[1];
        out_f[f * 8 + 0] = A.x; out_f[f * 8 + 1] = A.y; out_f[f * 8 + 2] = A.z; out_f[f * 8 + 3] = A.w;
        out_f[f * 8 + 4] = B.x; out_f[f * 8 + 5] = B.y; out_f[f * 8 + 6] = B.z; out_f[f * 8 + 7] = B.w;
        float sq = A.x * A.x + A.y * A.y + A.z * A.z + A.w * A.w +
                   B.x * B.x + B.y * B.y + B.z * B.z + B.w * B.w;
        sq += __shfl_xor_sync(0xffffffffu, sq, 1);
        sq += __shfl_xor_sync(0xffffffffu, sq, 2);
        float coef = (sq / (1.0f + sq)) * rsqrtf(sq + 1e-8f);
#pragma unroll
        for (int k = 0; k < 8; k++) out_f[f * 8 + k] *= coef;
    }

    float s_f[32];
#pragma unroll
    for (int k = 0; k < 32; k++) s_f[k] = 0.0f;

    const uint4* U = (const uint4*)g_uhat;
    const int ibase = blockIdx.x * 128 + w * 32;

    // prefetch first row: (b,i) tile = 128 uint4, chunk f: U[base + f*32 + lane]
    size_t rowidx = ((size_t)b * Ic + ibase) * 128;
    uint4 cur[4];
#pragma unroll
    for (int f = 0; f < 4; f++) cur[f] = U[rowidx + f * 32 + lane];

#pragma unroll 1
    for (int ii = 0; ii < 32; ii++) {
        const int i = ibase + ii;
        const int inext = (ii < 31) ? i + 1 : i;
        size_t nrow = ((size_t)b * Ic + inext) * 128;
        uint4 nxt[4];
#pragma unroll
        for (int f = 0; f < 4; f++) nxt[f] = U[nrow + f * 32 + lane];

        // partial dots p[f] = sum_{v in octet} u[8f+j][v] * out[8f+j][v]
        float p[4];
#pragma unroll
        for (int f = 0; f < 4; f++) {
            const __half2* h = (const __half2*)&cur[f];
            float acc = 0.f;
#pragma unroll
            for (int k = 0; k < 4; k++) {
                float2 fv = __half22float2(h[k]);
                acc = fmaf(fv.x, out_f[f * 8 + 2 * k], acc);
                acc = fmaf(fv.y, out_f[f * 8 + 2 * k + 1], acc);
            }
            p[f] = acc;
        }
        // reduce over the 4 v-quartets (lanes j*4..j*4+3)
#pragma unroll
        for (int f = 0; f < 4; f++) {
            p[f] += __shfl_xor_sync(0xffffffffu, p[f], 1);
            p[f] += __shfl_xor_sync(0xffffffffu, p[f], 2);
        }
        // add prior logits (iter 2)
        if (iter == 2) {
            const float* lg = g_logits + ((size_t)b * Ic + i) * Oc;
#pragma unroll
            for (int f = 0; f < 4; f++) p[f] += lg[8 * f + j];
        }
        // softmax over all 32 o (4 per lane-group, 8 groups)
        float m = fmaxf(fmaxf(p[0], p[1]), fmaxf(p[2], p[3]));
        m = fmaxf(m, __shfl_xor_sync(0xffffffffu, m, 4));
        m = fmaxf(m, __shfl_xor_sync(0xffffffffu, m, 8));
        m = fmaxf(m, __shfl_xor_sync(0xffffffffu, m, 16));
        float e0 = __expf(p[0] - m), e1 = __expf(p[1] - m);
        float e2 = __expf(p[2] - m), e3 = __expf(p[3] - m);
        float sum = e0 + e1 + e2 + e3;
        sum += __shfl_xor_sync(0xffffffffu, sum, 4);
        sum += __shfl_xor_sync(0xffffffffu, sum, 8);
        sum += __shfl_xor_sync(0xffffffffu, sum, 16);
        float inv = __frcp_rn(sum);
        float c[4] = {e0 * inv, e1 * inv, e2 * inv, e3 * inv};

        // s_next fragments += c[f] * u
#pragma unroll
        for (int f = 0; f < 4; f++) {
            const __half2* h = (const __half2*)&cur[f];
#pragma unroll
            for (int k = 0; k < 4; k++) {
                float2 fv = __half22float2(h[k]);
                s_f[f * 8 + 2 * k]     = fmaf(c[f], fv.x, s_f[f * 8 + 2 * k]);
                s_f[f * 8 + 2 * k + 1] = fmaf(c[f], fv.y, s_f[f * 8 + 2 * k + 1]);
            }
        }
        // iter 1: persist logits b1 = a0 (thread writes its o = 8q+j slot)
        if (iter == 1)
            g_logits[((size_t)b * Ic + i) * Oc + 8 * q + j] = p[q];

#pragma unroll
        for (int f = 0; f < 4; f++) cur[f] = nxt[f];
    }

#pragma unroll
    for (int f = 0; f < 4; f++)
#pragma unroll
        for (int k = 0; k < 8; k++)
            atomicAdd(&s_next[((b * Oc + 8 * f + j) * Vc) + 8 * q + k], s_f[f * 8 + k]);
}

// ---------------------------------------------------------------------
// final squash of s2 -> output
__global__ __launch_bounds__(256) void squash_out_kernel(float* __restrict__ out) {
    int g = blockIdx.x * 8 + (threadIdx.x >> 5);   // (b*32+o)
    int lane = threadIdx.x & 31;
    float s = g_sbuf[2][g * 32 + lane];
    float sq = s * s;
#pragma unroll
    for (int st = 16; st >= 1; st >>= 1) sq += __shfl_xor_sync(0xffffffffu, sq, st);
    out[g * 32 + lane] = (sq / (1.0f + sq)) * rsqrtf(sq + 1e-8f) * s;
}

// ---------------------------------------------------------------------
extern "C" void kernel_launch(void* const* d_in, const int* in_sizes, int n_in,
                              void* d_out, int out_size) {
    const float* x = (const float*)d_in[0];
    const float* W = (const float*)d_in[1];
    if (n_in >= 2 && in_sizes[0] > in_sizes[1]) {
        x = (const float*)d_in[1];
        W = (const float*)d_in[0];
    }
    float* out = (float*)d_out;

    zero_s_kernel<<<384, 256>>>();
    k1_gemm<<<dim3(Ic / 8, Oc), 256>>>(x, W);       // u_hat(fp16) + s0
    route_kernel<<<dim3(Ic / 128, Bc), 128>>>(1);   // squash(s0) -> a0 -> b1 -> c1 -> s1
    route_kernel<<<dim3(Ic / 128, Bc), 128>>>(2);   // squash(s1) -> a1 -> b2 -> c2 -> s2
    squash_out_kernel<<<128, 256>>>(out);           // out = squash(s2)
}

// round 4
// speedup vs baseline: 1.0480x; 1.0398x over previous
#include <cuda_runtime.h>
#include <cuda_fp16.h>
#include <math.h>

#define Bc 32
#define Oc 32
#define Ic 2048
#define Vc 32
#define Dc 16

// ---- scratch (static device arrays; no allocation anywhere) ----
// u_hat fp16, layout [b][i][o][v] : one (b,i) tile = 1024 halfs = 2KB contiguous
__device__ __half g_uhat[(size_t)Bc * Ic * Oc * Vc];   // 128 MB
__device__ float  g_logits[(size_t)Bc * Ic * Oc];      // [b][i][o], 8 MB
__device__ float  g_sbuf[3][Bc * Oc * Vc];             // s0, s1, s2

// ---------------------------------------------------------------------
__global__ void zero_s_kernel() {
    int i = blockIdx.x * blockDim.x + threadIdx.x;
    if (i < 3 * Bc * Oc * Vc) ((float*)g_sbuf)[i] = 0.0f;
}

// ---------------------------------------------------------------------
// K1: u_hat[b,i,o,v] = sum_d W[o,i,v,d] * x[b,i,d]  (fp32 math, fp16 store)
//     fused with s0[b,o,v] += (1/32) * sum_i u_hat.
// GRID SWAP vs R3: blockIdx.x = o (fast), blockIdx.y = i-tile, so the 32
// consecutive blocks sharing one x-tile run close together -> x hits L2.
__global__ __launch_bounds__(256) void k1_gemm(const float* __restrict__ x,
                                               const float* __restrict__ W) {
    __shared__ float4 Ws4[8 * 4 * 32];                 // [i][d4][v] 16 KB
    __shared__ unsigned long long Xp[16 * 8 * 16];     // [bpair][i][d] packed 16 KB

    const int o = blockIdx.x;
    const int i0 = blockIdx.y * 8;
    const int t = threadIdx.x;

    const float4* Wg = reinterpret_cast<const float4*>(W) +
                       ((size_t)o * Ic + i0) * (Vc * Dc / 4);
#pragma unroll
    for (int k = 0; k < 4; k++) {
        int j = t + k * 256;
        int i = j >> 7;
        int rem = j & 127;
        int v = rem >> 2;
        int d4 = rem & 3;
        Ws4[(i * 4 + d4) * 32 + v] = Wg[j];
    }
    const float4* Xg = reinterpret_cast<const float4*>(x);
#pragma unroll
    for (int k = 0; k < 4; k++) {
        int j = t + k * 256;
        int b = j >> 5;
        int r = j & 31;
        int il = r >> 2, d4 = r & 3;
        float4 val = Xg[(size_t)b * (Ic * Dc / 4) + i0 * 4 + r];
        float* dst = ((float*)&Xp[((b >> 1) * 8 + il) * 16 + d4 * 4]) + (b & 1);
        dst[0] = val.x; dst[2] = val.y; dst[4] = val.z; dst[6] = val.w;
    }
    __syncthreads();

    const int w = t >> 5;
    const int lane = t & 31;
    const int bbase = w * 4;

    float s0 = 0.f, s1 = 0.f, s2 = 0.f, s3 = 0.f;

#pragma unroll 1
    for (int i = 0; i < 8; i++) {
        float4 w0 = Ws4[(i * 4 + 0) * 32 + lane];
        float4 w1 = Ws4[(i * 4 + 1) * 32 + lane];
        float4 w2 = Ws4[(i * 4 + 2) * 32 + lane];
        float4 w3 = Ws4[(i * 4 + 3) * 32 + lane];
        float wv[16] = {w0.x, w0.y, w0.z, w0.w, w1.x, w1.y, w1.z, w1.w,
                        w2.x, w2.y, w2.z, w2.w, w3.x, w3.y, w3.z, w3.w};
        unsigned long long a01 = 0ull, a23 = 0ull;
        const unsigned long long* x0 = Xp + ((w * 2 + 0) * 8 + i) * 16;
        const unsigned long long* x1 = Xp + ((w * 2 + 1) * 8 + i) * 16;
#pragma unroll
        for (int d = 0; d < 16; d++) {
            unsigned long long wp;
            asm("mov.b64 %0, {%1, %1};" : "=l"(wp) : "f"(wv[d]));
            asm("fma.rn.f32x2 %0, %1, %2, %0;" : "+l"(a01) : "l"(wp), "l"(x0[d]));
            asm("fma.rn.f32x2 %0, %1, %2, %0;" : "+l"(a23) : "l"(wp), "l"(x1[d]));
        }
        float u0, u1, u2, u3;
        asm("mov.b64 {%0, %1}, %2;" : "=f"(u0), "=f"(u1) : "l"(a01));
        asm("mov.b64 {%0, %1}, %2;" : "=f"(u2), "=f"(u3) : "l"(a23));

        size_t ib = (size_t)(i0 + i) * (Oc * Vc) + o * Vc + lane;
        const size_t bstride = (size_t)Ic * Oc * Vc;
        g_uhat[(size_t)(bbase + 0) * bstride + ib] = __float2half_rn(u0);
        g_uhat[(size_t)(bbase + 1) * bstride + ib] = __float2half_rn(u1);
        g_uhat[(size_t)(bbase + 2) * bstride + ib] = __float2half_rn(u2);
        g_uhat[(size_t)(bbase + 3) * bstride + ib] = __float2half_rn(u3);
        s0 += u0; s1 += u1; s2 += u2; s3 += u3;
    }
    const float scale = 1.0f / (float)Oc;
    atomicAdd(&g_sbuf[0][((bbase + 0) * Oc + o) * Vc + lane], s0 * scale);
    atomicAdd(&g_sbuf[0][((bbase + 1) * Oc + o) * Vc + lane], s1 * scale);
    atomicAdd(&g_sbuf[0][((bbase + 2) * Oc + o) * Vc + lane], s2 * scale);
    atomicAdd(&g_sbuf[0][((bbase + 3) * Oc + o) * Vc + lane], s3 * scale);
}

// ---------------------------------------------------------------------
// cp.async helpers
__device__ __forceinline__ unsigned smem_u32p(const void* p) {
    return (unsigned)__cvta_generic_to_shared(p);
}
#define CP_ASYNC16(dst, src) \
    asm volatile("cp.async.cg.shared.global [%0], [%1], 16;" :: "r"(dst), "l"(src))
#define CP_COMMIT() asm volatile("cp.async.commit_group;" ::: "memory")
#define CP_WAIT1()  asm volatile("cp.async.wait_group 1;" ::: "memory")
#define CP_WAIT0()  asm volatile("cp.async.wait_group 0;" ::: "memory")

// ---------------------------------------------------------------------
// Routing pass, fused: squash(s_prev) inline; a; logits; softmax(o); s_next.
// Block: 256 thr = 8 warps, warp owns 8 consecutive i-rows with a 2-stage
// per-warp cp.async ring (2KB/stage). Grid (Ic/64, B) = 1024 blocks.
// Thread (j=lane/4, q=lane%4) owns (o = 8f+j, v-octet q), f=0..3.
__global__ __launch_bounds__(256, 2) void route_kernel(int iter) {
    // 8 warps * 2 stages * 512 floats ring; reused as [w][m][lane] reduction buf
    __shared__ __align__(16) float usm[8 * 1024];      // 32 KB

    const int b = blockIdx.y;
    const int t = threadIdx.x;
    const int w = t >> 5;
    const int lane = t & 31;
    const int j = lane >> 2;
    const int q = lane & 3;

    const float* s_prev = g_sbuf[iter - 1];
    float* s_next = g_sbuf[iter];

    // inline squash: out_f[f*8+k] = squash(s_prev)[o=8f+j][v=8q+k]
    float out_f[32];
#pragma unroll
    for (int f = 0; f < 4; f++) {
        const float4* p = (const float4*)(s_prev + ((b * Oc + 8 * f + j) * Vc + 8 * q));
        float4 A = p[0], B = p[1];
        out_f[f * 8 + 0] = A.x; out_f[f * 8 + 1] = A.y; out_f[f * 8 + 2] = A.z; out_f[f * 8 + 3] = A.w;
        out_f[f * 8 + 4] = B.x; out_f[f * 8 + 5] = B.y; out_f[f * 8 + 6] = B.z; out_f[f * 8 + 7] = B.w;
        float sq = A.x * A.x + A.y * A.y + A.z * A.z + A.w * A.w +
                   B.x * B.x + B.y * B.y + B.z * B.z + B.w * B.w;
        sq += __shfl_xor_sync(0xffffffffu, sq, 1);
        sq += __shfl_xor_sync(0xffffffffu, sq, 2);
        float coef = (sq / (1.0f + sq)) * rsqrtf(sq + 1e-8f);
#pragma unroll
        for (int k = 0; k < 8; k++) out_f[f * 8 + k] *= coef;
    }

    float s_f[32];
#pragma unroll
    for (int k = 0; k < 32; k++) s_f[k] = 0.0f;

    const int ibase = blockIdx.x * 64 + w * 8;
    const char* gsrc = (const char*)g_uhat + ((size_t)b * Ic + ibase) * 2048;
    const unsigned ring = smem_u32p(usm) + w * 4096;   // per-warp 2 stages x 2KB
    float* ringf = usm + w * 1024;

    // prologue: row 0 -> stage 0
#pragma unroll
    for (int k = 0; k < 4; k++)
        CP_ASYNC16(ring + lane * 16 + k * 512, gsrc + lane * 16 + k * 512);
    CP_COMMIT();

#pragma unroll 1
    for (int r = 0; r < 8; r++) {
        __syncwarp();  // all lanes done reading the stage we're about to overwrite
        if (r + 1 < 8) {
            const char* src = gsrc + (size_t)(r + 1) * 2048;
            unsigned dst = ring + ((r + 1) & 1) * 2048;
#pragma unroll
            for (int k = 0; k < 4; k++)
                CP_ASYNC16(dst + lane * 16 + k * 512, src + lane * 16 + k * 512);
            CP_COMMIT();
            CP_WAIT1();
        } else {
            CP_WAIT0();
        }
        __syncwarp();

        const int i = ibase + r;
        const float* row = ringf + (r & 1) * 512;

        uint4 cur[4];
#pragma unroll
        for (int f = 0; f < 4; f++)
            cur[f] = *(const uint4*)(row + (f * 32 + lane) * 4);

        // p[f] = partial dot over this thread's v-octet
        float p[4];
#pragma unroll
        for (int f = 0; f < 4; f++) {
            const __half2* h = (const __half2*)&cur[f];
            float acc = 0.f;
#pragma unroll
            for (int k = 0; k < 4; k++) {
                float2 fv = __half22float2(h[k]);
                acc = fmaf(fv.x, out_f[f * 8 + 2 * k], acc);
                acc = fmaf(fv.y, out_f[f * 8 + 2 * k + 1], acc);
            }
            p[f] = acc;
        }
#pragma unroll
        for (int f = 0; f < 4; f++) {
            p[f] += __shfl_xor_sync(0xffffffffu, p[f], 1);
            p[f] += __shfl_xor_sync(0xffffffffu, p[f], 2);
        }
        if (iter == 2) {
            const float* lg = g_logits + ((size_t)b * Ic + i) * Oc;
#pragma unroll
            for (int f = 0; f < 4; f++) p[f] += lg[8 * f + j];
        }
        // softmax over all 32 o
        float m = fmaxf(fmaxf(p[0], p[1]), fmaxf(p[2], p[3]));
        m = fmaxf(m, __shfl_xor_sync(0xffffffffu, m, 4));
        m = fmaxf(m, __shfl_xor_sync(0xffffffffu, m, 8));
        m = fmaxf(m, __shfl_xor_sync(0xffffffffu, m, 16));
        float e0 = __expf(p[0] - m), e1 = __expf(p[1] - m);
        float e2 = __expf(p[2] - m), e3 = __expf(p[3] - m);
        float sum = e0 + e1 + e2 + e3;
        sum += __shfl_xor_sync(0xffffffffu, sum, 4);
        sum += __shfl_xor_sync(0xffffffffu, sum, 8);
        sum += __shfl_xor_sync(0xffffffffu, sum, 16);
        float inv = __frcp_rn(sum);
        float c[4] = {e0 * inv, e1 * inv, e2 * inv, e3 * inv};

#pragma unroll
        for (int f = 0; f < 4; f++) {
            const __half2* h = (const __half2*)&cur[f];
#pragma unroll
            for (int k = 0; k < 4; k++) {
                float2 fv = __half22float2(h[k]);
                s_f[f * 8 + 2 * k]     = fmaf(c[f], fv.x, s_f[f * 8 + 2 * k]);
                s_f[f * 8 + 2 * k + 1] = fmaf(c[f], fv.y, s_f[f * 8 + 2 * k + 1]);
            }
        }
        if (iter == 1)
            g_logits[((size_t)b * Ic + i) * Oc + 8 * q + j] = p[q];
    }

    // block-level s reduction: usm reused as [w][m][lane] (conflict-free)
    __syncthreads();
#pragma unroll
    for (int m = 0; m < 32; m++)
        usm[w * 1024 + m * 32 + lane] = s_f[m];
    __syncthreads();

    {
        const int lr = t & 31;
        const int m0 = (t >> 5) * 4;
#pragma unroll
        for (int mm = 0; mm < 4; mm++) {
            int m = m0 + mm;
            float acc = 0.f;
#pragma unroll
            for (int ww = 0; ww < 8; ww++) acc += usm[ww * 1024 + m * 32 + lr];
            int o = 8 * (m >> 3) + (lr >> 2);
            int v = 8 * (lr & 3) + (m & 7);
            atomicAdd(&s_next[(b * Oc + o) * Vc + v], acc);
        }
    }
}

// ---------------------------------------------------------------------
__global__ __launch_bounds__(256) void squash_out_kernel(float* __restrict__ out) {
    int g = blockIdx.x * 8 + (threadIdx.x >> 5);
    int lane = threadIdx.x & 31;
    float s = g_sbuf[2][g * 32 + lane];
    float sq = s * s;
#pragma unroll
    for (int st = 16; st >= 1; st >>= 1) sq += __shfl_xor_sync(0xffffffffu, sq, st);
    out[g * 32 + lane] = (sq / (1.0f + sq)) * rsqrtf(sq + 1e-8f) * s;
}

// ---------------------------------------------------------------------
extern "C" void kernel_launch(void* const* d_in, const int* in_sizes, int n_in,
                              void* d_out, int out_size) {
    const float* x = (const float*)d_in[0];
    const float* W = (const float*)d_in[1];
    if (n_in >= 2 && in_sizes[0] > in_sizes[1]) {
        x = (const float*)d_in[1];
        W = (const float*)d_in[0];
    }
    float* out = (float*)d_out;

    zero_s_kernel<<<384, 256>>>();
    k1_gemm<<<dim3(Oc, Ic / 8), 256>>>(x, W);       // u_hat(fp16) + s0 (grid swapped)
    route_kernel<<<dim3(Ic / 64, Bc), 256>>>(1);    // squash(s0)->a0->b1->c1->s1
    route_kernel<<<dim3(Ic / 64, Bc), 256>>>(2);    // squash(s1)->a1->b2->c2->s2
    squash_out_kernel<<<128, 256>>>(out);           // out = squash(s2)
}